// round 15
// baseline (speedup 1.0000x reference)
#include <cuda_runtime.h>
#include <cuda_fp16.h>
#include <math.h>
#include <stdint.h>

#define B_    2
#define T_    2048
#define C_    2048
#define H_    16
#define KVH_  4
#define D_    128
#define GROUPS_ (H_/KVH_)
#define EPS_  1.1920929e-07f

#define GK    2048              // K dim in halves
#define GKU   1024              // K dim in u32 (fp16 pairs)
#define BKU   32                // u32 per iter (= 64 halves)
#define NIT   32

// ---------------- scratch (device globals; fp16 data as u32 pairs) ---------
__device__ unsigned g_xc  [B_*T_*GKU];
__device__ unsigned g_wqc [H_*D_*GKU];
__device__ unsigned g_wkc [KVH_*D_*GKU];
__device__ unsigned g_wvc [KVH_*D_*GKU];
__device__ unsigned g_woc [C_*GKU];
__device__ unsigned g_qt  [B_*T_*H_*64];        // [B,H,T,64u32] natural pairs
__device__ unsigned g_kt  [B_*T_*KVH_*64];      // [B,KVH,T,64u32] d-pair-PERMUTED
__device__ unsigned g_vperm[B_*KVH_*32*128*40]; // [B,KVH,ktile,128 d,40]
__device__ unsigned g_y   [B_*T_*H_*64];        // [B,T,H*64u32] pair-PERMUTED

// ---------------------------------------------------------------------------
// helpers
// ---------------------------------------------------------------------------
__device__ __forceinline__ unsigned pk2h(float a, float b) {
    __half2 h = __floats2half2_rn(a, b);
    return *(unsigned*)&h;
}

__device__ __forceinline__ float ex2(float x) {
    float y;
    asm("ex2.approx.ftz.f32 %0, %1;" : "=f"(y) : "f"(x));
    return y;
}

__device__ __forceinline__ uint32_t smem_u32(const void* p) {
    uint32_t a;
    asm("{ .reg .u64 t; cvta.to.shared.u64 t, %1; cvt.u32.u64 %0, t; }"
        : "=r"(a) : "l"(p));
    return a;
}

__device__ __forceinline__ void mma16(float* d, const unsigned* a, const unsigned* b) {
    asm volatile(
        "mma.sync.aligned.m16n8k16.row.col.f32.f16.f16.f32 "
        "{%0,%1,%2,%3}, {%4,%5,%6,%7}, {%8,%9}, {%0,%1,%2,%3};\n"
        : "+f"(d[0]), "+f"(d[1]), "+f"(d[2]), "+f"(d[3])
        : "r"(a[0]), "r"(a[1]), "r"(a[2]), "r"(a[3]), "r"(b[0]), "r"(b[1]));
}

#define CPC()  asm volatile("cp.async.commit_group;" ::: "memory")
#define CPW1() asm volatile("cp.async.wait_group 1;" ::: "memory")
#define CPW0() asm volatile("cp.async.wait_group 0;" ::: "memory")

// ---------------------------------------------------------------------------
// Fused fp16 pre-convert + pair-PERMUTE (one launch).
// ---------------------------------------------------------------------------
#define NX16  (B_*T_*C_/16)
#define NWQ16 (H_*D_*C_/16)
#define NWK16 (KVH_*D_*C_/16)
#define NCVT16 (NX16 + 2*NWQ16 + 2*NWK16)

__global__ __launch_bounds__(256) void cvt_all_kernel(
    const float4* __restrict__ x,  uint4* __restrict__ xc,
    const float4* __restrict__ wq, uint4* __restrict__ wqc,
    const float4* __restrict__ wk, uint4* __restrict__ wkc,
    const float4* __restrict__ wv, uint4* __restrict__ wvc,
    const float4* __restrict__ wo, uint4* __restrict__ woc)
{
    int i = blockIdx.x * 256 + threadIdx.x;
    const float4* src; uint4* dst; int off;
    if (i < NX16)                           { src = x;  dst = xc;  off = 0; }
    else if (i < NX16 + NWQ16)              { src = wq; dst = wqc; off = NX16; }
    else if (i < NX16 + NWQ16 + NWK16)      { src = wk; dst = wkc; off = NX16 + NWQ16; }
    else if (i < NX16 + NWQ16 + 2*NWK16)    { src = wv; dst = wvc; off = NX16 + NWQ16 + NWK16; }
    else                                    { src = wo; dst = woc; off = NX16 + NWQ16 + 2*NWK16; }
    int j = i - off;
    float4 v0 = src[4*j], v1 = src[4*j+1], v2 = src[4*j+2], v3 = src[4*j+3];
    dst[2*j]   = make_uint4(pk2h(v0.x, v0.y), pk2h(v2.x, v2.y),
                            pk2h(v0.z, v0.w), pk2h(v2.z, v2.w));
    dst[2*j+1] = make_uint4(pk2h(v1.x, v1.y), pk2h(v3.x, v3.y),
                            pk2h(v1.z, v1.w), pk2h(v3.z, v3.w));
}

// ---------------------------------------------------------------------------
// fp16 GEMM machinery (R14-proven, unchanged).
// ---------------------------------------------------------------------------
#define GST 40
#define TAW (256 * GST)
#define TWW (128 * GST)
#define STGW (TAW + TWW)
#define STGB (STGW * 4)
#define GEMM_SMEM (3 * STGB)             // 184320 B

__device__ __forceinline__ void issue_tile(uint32_t stg, const unsigned* Ab,
                                           const unsigned* Wb, int k0u, int tid)
{
    #pragma unroll
    for (int l = 0; l < 8; l++) {
        int idx = tid + l * 256;
        int r  = idx >> 3;
        int c4 = (idx & 7) * 4;
        asm volatile("cp.async.cg.shared.global [%0], [%1], 16;"
            :: "r"(stg + (uint32_t)(r * GST + c4) * 4),
               "l"(Ab + (size_t)r * GKU + k0u + c4));
    }
    #pragma unroll
    for (int l = 0; l < 4; l++) {
        int idx = tid + l * 256;
        int r  = idx >> 3;
        int c4 = (idx & 7) * 4;
        asm volatile("cp.async.cg.shared.global [%0], [%1], 16;"
            :: "r"(stg + (uint32_t)(TAW + r * GST + c4) * 4),
               "l"(Wb + (size_t)r * GKU + k0u + c4));
    }
}

__device__ __forceinline__ void mma_tile(const unsigned* As, const unsigned* Ws,
                                         int wm, int wn, int g, int t,
                                         float acc[4][8][4]) {
    #pragma unroll
    for (int s16 = 0; s16 < 4; s16++) {
        const int ko = s16 * 8 + 2 * t;
        unsigned a[4][4], b[8][2];
        #pragma unroll
        for (int mi = 0; mi < 4; mi++) {
            int r = wm + mi * 16;
            uint2 v0 = *(const uint2*)&As[(r + g)     * GST + ko];
            uint2 v1 = *(const uint2*)&As[(r + g + 8) * GST + ko];
            a[mi][0] = v0.x; a[mi][2] = v0.y;
            a[mi][1] = v1.x; a[mi][3] = v1.y;
        }
        #pragma unroll
        for (int j = 0; j < 8; j++) {
            uint2 v = *(const uint2*)&Ws[(wn + j * 8 + g) * GST + ko];
            b[j][0] = v.x; b[j][1] = v.y;
        }
        #pragma unroll
        for (int mi = 0; mi < 4; mi++)
            #pragma unroll
            for (int j = 0; j < 8; j++)
                mma16(acc[mi][j], a[mi], b[j]);
    }
}

#define GEMM_MAINLOOP(Ab, Wb)                                                  \
    float acc[4][8][4];                                                        \
    _Pragma("unroll")                                                          \
    for (int mi = 0; mi < 4; mi++)                                             \
        _Pragma("unroll")                                                      \
        for (int j = 0; j < 8; j++)                                            \
            _Pragma("unroll")                                                  \
            for (int c = 0; c < 4; c++) acc[mi][j][c] = 0.f;                   \
    {                                                                          \
        const uint32_t sb0 = smem_u32(sm);                                     \
        issue_tile(sb0,        Ab, Wb, 0,   tid); CPC();                       \
        issue_tile(sb0 + STGB, Ab, Wb, BKU, tid); CPC();                       \
        for (int it = 0; it < NIT; it++) {                                     \
            CPW1();                                                            \
            __syncthreads();                                                   \
            const int s = it - (it / 3) * 3;                                   \
            const unsigned* Ac = sm + s * STGW;                                \
            const unsigned* Wc = Ac + TAW;                                     \
            mma_tile(Ac, Wc, wm, wn, g, t, acc);                               \
            if (it + 2 < NIT) {                                                \
                const int sn = (it + 2) - ((it + 2) / 3) * 3;                  \
                issue_tile(sb0 + sn * STGB, Ab, Wb, (it + 2) * BKU, tid);      \
            }                                                                  \
            CPC();                                                             \
        }                                                                      \
    }

// ---------------------------------------------------------------------------
// Fused QKV projection + RoPE + RMSNorm epilogue (R14-proven, unchanged).
// ---------------------------------------------------------------------------
__global__ __launch_bounds__(256, 1) void qkv_gemm(
    const unsigned* __restrict__ x,
    const unsigned* __restrict__ Wq, const unsigned* __restrict__ Wk,
    const unsigned* __restrict__ Wv,
    const float* __restrict__ cosb, const float* __restrict__ sinb,
    unsigned* __restrict__ qt, unsigned* __restrict__ kt,
    unsigned* __restrict__ vperm)
{
    extern __shared__ unsigned sm[];

    const int tid  = threadIdx.x;
    const int lane = tid & 31;
    const int wid  = tid >> 5;
    const int g    = lane >> 2;
    const int t    = lane & 3;
    const int wm = (wid & 3) * 64;
    const int wn = (wid >> 2) * 64;
    const int m0 = blockIdx.y * 256;
    const int nb = blockIdx.x;

    const unsigned* W;
    if (nb < 16)      W = Wq + (size_t)nb * 128 * GKU;
    else if (nb < 20) W = Wk + (size_t)(nb - 16) * 128 * GKU;
    else              W = Wv + (size_t)(nb - 20) * 128 * GKU;
    const unsigned* Ab = x + (size_t)m0 * GKU;
    const unsigned* Wb = W;

    GEMM_MAINLOOP(Ab, Wb)

    __syncthreads();
    float* St = (float*)sm;
    #pragma unroll
    for (int mi = 0; mi < 4; mi++) {
        int r0 = wm + mi * 16 + g;
        #pragma unroll
        for (int j = 0; j < 8; j++) {
            int cc = wn + j * 8 + 2 * t;
            St[r0 * 132 + cc]           = acc[mi][j][0];
            St[r0 * 132 + cc + 1]       = acc[mi][j][1];
            St[(r0 + 8) * 132 + cc]     = acc[mi][j][2];
            St[(r0 + 8) * 132 + cc + 1] = acc[mi][j][3];
        }
    }
    __syncthreads();

    if (nb >= 20) {
        const int kvh = nb - 20;
        const int bidx = m0 >> 11;
        const int kt0  = (m0 & (T_ - 1)) >> 6;
        #pragma unroll
        for (int l = 0; l < 64; l++) {
            int idx = tid + l * 256;
            int c   = idx & 31;
            int d   = (idx >> 5) & 127;
            int kt4 = idx >> 12;
            int pl  = ((c & 7) >> 1) + ((c & 1) << 2);
            int kl  = (c >> 3) * 16 + 2 * pl;
            int row = kt4 * 64 + kl;
            unsigned val = pk2h(St[row * 132 + d], St[(row + 1) * 132 + d]);
            vperm[((size_t)((bidx * KVH_ + kvh) * 32 + kt0 + kt4) * 128 + d) * 40 + c] = val;
        }
        return;
    }

    const float scale = (nb < 16) ? 0.12751744843f : 1.0f;
    #pragma unroll
    for (int round = 0; round < 2; round++) {
        const int r  = (tid >> 1) + round * 128;
        const int hf = tid & 1;
        const int m  = m0 + r;
        const int bb = m >> 11;
        const int tt = m & (T_ - 1);

        const float* cr = cosb + tt * 64 + hf * 32;
        const float* sr = sinb + tt * 64 + hf * 32;
        const float* x1p = St + r * 132 + hf * 32;
        const float* x2p = x1p + 64;

        float o1[32], o2[32];
        float ss = 0.f;
        #pragma unroll
        for (int jj = 0; jj < 32; jj += 4) {
            float4 x1 = *(const float4*)(x1p + jj);
            float4 x2 = *(const float4*)(x2p + jj);
            float4 cv = *(const float4*)(cr + jj);
            float4 sv = *(const float4*)(sr + jj);
            float a0 = x1.x * cv.x + x2.x * sv.x, b0 = x2.x * cv.x - x1.x * sv.x;
            float a1 = x1.y * cv.y + x2.y * sv.y, b1 = x2.y * cv.y - x1.y * sv.y;
            float a2 = x1.z * cv.z + x2.z * sv.z, b2 = x2.z * cv.z - x1.z * sv.z;
            float a3 = x1.w * cv.w + x2.w * sv.w, b3 = x2.w * cv.w - x1.w * sv.w;
            o1[jj] = a0; o1[jj+1] = a1; o1[jj+2] = a2; o1[jj+3] = a3;
            o2[jj] = b0; o2[jj+1] = b1; o2[jj+2] = b2; o2[jj+3] = b3;
            ss += a0*a0 + b0*b0 + a1*a1 + b1*b1 + a2*a2 + b2*b2 + a3*a3 + b3*b3;
        }
        ss += __shfl_xor_sync(0xffffffffu, ss, 1);
        const float rr = rsqrtf(ss * (1.f / 128.f) + EPS_) * scale;

        if (nb < 16) {
            unsigned* ob = qt + (((size_t)(bb * H_ + nb) * T_ + tt) * 64);
            #pragma unroll
            for (int pj = 0; pj < 16; pj += 4) {
                *(uint4*)(ob + hf * 16 + pj) = make_uint4(
                    pk2h(o1[2*pj]   * rr, o1[2*pj+1] * rr),
                    pk2h(o1[2*pj+2] * rr, o1[2*pj+3] * rr),
                    pk2h(o1[2*pj+4] * rr, o1[2*pj+5] * rr),
                    pk2h(o1[2*pj+6] * rr, o1[2*pj+7] * rr));
                *(uint4*)(ob + 32 + hf * 16 + pj) = make_uint4(
                    pk2h(o2[2*pj]   * rr, o2[2*pj+1] * rr),
                    pk2h(o2[2*pj+2] * rr, o2[2*pj+3] * rr),
                    pk2h(o2[2*pj+4] * rr, o2[2*pj+5] * rr),
                    pk2h(o2[2*pj+6] * rr, o2[2*pj+7] * rr));
            }
        } else {
            unsigned* ob = kt + (((size_t)(bb * KVH_ + (nb - 16)) * T_ + tt) * 64);
            #pragma unroll
            for (int pj = 0; pj < 16; pj++) {
                int p1 = hf * 16 + pj;
                int pos1 = (p1 & ~7) + 2 * (p1 & 3) + ((p1 >> 2) & 1);
                ob[pos1] = pk2h(o1[2*pj] * rr, o1[2*pj+1] * rr);
                int p2 = p1 + 32;
                int pos2 = (p2 & ~7) + 2 * (p2 & 3) + ((p2 >> 2) & 1);
                ob[pos2] = pk2h(o2[2*pj] * rr, o2[2*pj+1] * rr);
            }
        }
    }
}

// ---------------------------------------------------------------------------
// Plain GEMM (output projection; R14-proven, unchanged). grid = (16, 16)
// ---------------------------------------------------------------------------
__global__ __launch_bounds__(256, 1) void out_gemm(
    const unsigned* __restrict__ A, const unsigned* __restrict__ W,
    float* __restrict__ C, int N)
{
    extern __shared__ unsigned sm[];

    const int tid  = threadIdx.x;
    const int lane = tid & 31;
    const int wid  = tid >> 5;
    const int g    = lane >> 2;
    const int t    = lane & 3;
    const int wm = (wid & 3) * 64;
    const int wn = (wid >> 2) * 64;
    const int m0 = blockIdx.y * 256;
    const int n0 = blockIdx.x * 128;

    const unsigned* Ab = A + (size_t)m0 * GKU;
    const unsigned* Wb = W + (size_t)n0 * GKU;

    GEMM_MAINLOOP(Ab, Wb)

    #pragma unroll
    for (int mi = 0; mi < 4; mi++) {
        int r0 = m0 + wm + mi * 16 + g;
        #pragma unroll
        for (int j = 0; j < 8; j++) {
            int cc = n0 + wn + j * 8 + 2 * t;
            *(float2*)(C + (size_t)r0 * N + cc) =
                make_float2(acc[mi][j][0], acc[mi][j][1]);
            *(float2*)(C + (size_t)(r0 + 8) * N + cc) =
                make_float2(acc[mi][j][2], acc[mi][j][3]);
        }
    }
}

// ---------------------------------------------------------------------------
// Causal flash attention fp16 v2: S(kt+1) software-pipelined ahead of
// softmax(kt)/PV(kt); 3-stage K and V rings; Q in regs; ex2 softmax.
// ---------------------------------------------------------------------------
#define KST 72
#define VSTU 40
#define PST 40
#define KBUF (64 * KST)                 // 4608 u32 / stage
#define VBUF (128 * VSTU)               // 5120 u32 / stage
#define VS_OFF (3 * KBUF)               // 13824
#define PS_OFF (VS_OFF + 3 * VBUF)      // 29184
#define FLASH_SMEM ((PS_OFF + 128 * PST) * 4)   // 137216 B

__global__ __launch_bounds__(256, 1) void flash_fp16(
    const unsigned* __restrict__ Qt, const unsigned* __restrict__ Kt,
    const unsigned* __restrict__ Vperm, unsigned* __restrict__ Y)
{
    extern __shared__ unsigned smu[];

    const int tid  = threadIdx.x;
    const int lane = tid & 31;
    const int wid  = tid >> 5;
    const int g    = lane >> 2;
    const int t    = lane & 3;
    const int qb = (gridDim.x - 1) - blockIdx.x;   // heavy-first
    const int q0 = qb * 128;
    const int bh = blockIdx.y;
    const int b  = bh / H_;
    const int h  = bh % H_;
    const int kvh = h / GROUPS_;
    const int wr  = wid * 16;

    unsigned* Ps = smu + PS_OFF;
    const uint32_t sbase = smem_u32(smu);

    const unsigned* kbase = Kt + ((size_t)(b * KVH_ + kvh) * T_) * 64;
    const unsigned* vblock = Vperm + (size_t)(b * KVH_ + kvh) * 32 * VBUF;

    // ---- stage Q (natural pairs) via smem (area reused by K ring later) ----
    unsigned qreg[8][4];
    {
        const unsigned* qbase = Qt + ((size_t)bh * T_ + q0) * 64;
        #pragma unroll
        for (int l = 0; l < 8; l++) {
            int idx = tid + l * 256;       // 128 rows x 16 uint4 chunks
            int r  = idx >> 4;
            int c4 = (idx & 15) * 4;
            *(uint4*)&smu[r * 64 + c4] = *(const uint4*)(qbase + (size_t)r * 64 + c4);
        }
        __syncthreads();
        #pragma unroll
        for (int s16 = 0; s16 < 8; s16++) {
            qreg[s16][0] = smu[(wr + g)     * 64 + s16 * 8 + t];
            qreg[s16][1] = smu[(wr + g + 8) * 64 + s16 * 8 + t];
            qreg[s16][2] = smu[(wr + g)     * 64 + s16 * 8 + t + 4];
            qreg[s16][3] = smu[(wr + g + 8) * 64 + s16 * 8 + t + 4];
        }
        __syncthreads();
    }

    auto issue_kv = [&](int kt, int s) {
        const int k0 = kt * 64;
        const uint32_t kdst = sbase + (uint32_t)(s * KBUF) * 4;
        #pragma unroll
        for (int l = 0; l < 4; l++) {
            int idx = tid + l * 256;       // 64 rows x 16 chunks
            int r  = idx >> 4;
            int c4 = (idx & 15) * 4;
            asm volatile("cp.async.cg.shared.global [%0], [%1], 16;"
                :: "r"(kdst + (uint32_t)(r * KST + c4) * 4),
                   "l"(kbase + (size_t)(k0 + r) * 64 + c4));
        }
        const unsigned* vsrc = vblock + (size_t)kt * VBUF;
        const uint32_t vdst = sbase + (uint32_t)(VS_OFF + s * VBUF) * 4;
        #pragma unroll
        for (int l = 0; l < 5; l++) {
            int idx = tid + l * 256;       // 1280 chunks exactly
            asm volatile("cp.async.cg.shared.global [%0], [%1], 16;"
                :: "r"(vdst + (uint32_t)idx * 16),
                   "l"(vsrc + (size_t)idx * 4));
        }
    };

    auto compute_S = [&](float (*sc)[4], const unsigned* Kc) {
        #pragma unroll
        for (int j = 0; j < 8; j++)
            #pragma unroll
            for (int c = 0; c < 4; c++) sc[j][c] = 0.f;
        #pragma unroll
        for (int s16 = 0; s16 < 8; s16++) {
            #pragma unroll
            for (int j = 0; j < 8; j++) {
                uint2 kv = *(const uint2*)&Kc[(j * 8 + g) * KST + s16 * 8 + 2 * t];
                unsigned kb[2] = {kv.x, kv.y};
                mma16(sc[j], qreg[s16], kb);
            }
        }
    };

    float oacc[16][4];
    #pragma unroll
    for (int j = 0; j < 16; j++)
        #pragma unroll
        for (int c = 0; c < 4; c++) oacc[j][c] = 0.f;
    float mrow[2] = {-INFINITY, -INFINITY};
    float lrow[2] = {0.f, 0.f};

    const int nkt = qb * 2 + 2;           // always even

    issue_kv(0, 0); CPC();
    issue_kv(1, 1); CPC();
    CPW1();                               // kv(0) resident
    __syncthreads();

    float scA[8][4], scB[8][4];
    compute_S(scA, smu);                  // S(0) from K stage 0

    auto body = [&](int kt, float (*Scur)[4], float (*Snxt)[4]) {
        if (kt + 1 < nkt) {
            CPW0();                       // kv(kt+1) resident
            __syncthreads();              // also orders prior reads vs new writes
            if (kt + 2 < nkt) {
                int sn = (kt + 2) - ((kt + 2) / 3) * 3;
                issue_kv(kt + 2, sn);
            }
            CPC();
            int sn1 = (kt + 1) - ((kt + 1) / 3) * 3;
            compute_S(Snxt, smu + sn1 * KBUF);
        }

        const int k0 = kt * 64;
        if (kt >= nkt - 2) {
            int row0 = q0 + wr + g;
            int row1 = row0 + 8;
            #pragma unroll
            for (int j = 0; j < 8; j++) {
                int c0 = k0 + j * 8 + 2 * t;
                int c1 = c0 + 1;
                if (c0 > row0) Scur[j][0] = -1e30f;
                if (c1 > row0) Scur[j][1] = -1e30f;
                if (c0 > row1) Scur[j][2] = -1e30f;
                if (c1 > row1) Scur[j][3] = -1e30f;
            }
        }

        #pragma unroll
        for (int ri = 0; ri < 2; ri++) {
            const int i0 = ri * 2, i1 = ri * 2 + 1;
            float mx = -1e30f;
            #pragma unroll
            for (int j = 0; j < 8; j++)
                mx = fmaxf(mx, fmaxf(Scur[j][i0], Scur[j][i1]));
            mx = fmaxf(mx, __shfl_xor_sync(0xffffffffu, mx, 1));
            mx = fmaxf(mx, __shfl_xor_sync(0xffffffffu, mx, 2));
            float mnew = fmaxf(mrow[ri], mx);
            float alpha = ex2(mrow[ri] - mnew);
            float rs = 0.f;
            #pragma unroll
            for (int j = 0; j < 8; j++) {
                float p0 = ex2(Scur[j][i0] - mnew);
                float p1 = ex2(Scur[j][i1] - mnew);
                Scur[j][i0] = p0; Scur[j][i1] = p1;
                rs += p0 + p1;
            }
            rs += __shfl_xor_sync(0xffffffffu, rs, 1);
            rs += __shfl_xor_sync(0xffffffffu, rs, 2);
            lrow[ri] = lrow[ri] * alpha + rs;
            mrow[ri] = mnew;
            #pragma unroll
            for (int j = 0; j < 16; j++) {
                oacc[j][i0] *= alpha;
                oacc[j][i1] *= alpha;
            }
        }

        // ---- write P (fp16 pairs, key-pair-permuted positions) ----
        #pragma unroll
        for (int j = 0; j < 8; j++) {
            int pos = (j >> 1) * 8 + 2 * t + (j & 1);
            Ps[(wr + g)     * PST + pos] = pk2h(Scur[j][0], Scur[j][1]);
            Ps[(wr + g + 8) * PST + pos] = pk2h(Scur[j][2], Scur[j][3]);
        }
        __syncwarp();

        // ---- O += P . V ----
        const int sv = kt - (kt / 3) * 3;
        const unsigned* Vc = smu + VS_OFF + sv * VBUF;
        #pragma unroll
        for (int s16 = 0; s16 < 4; s16++) {
            uint2 u0 = *(const uint2*)&Ps[(wr + g)     * PST + s16 * 8 + 2 * t];
            uint2 u1 = *(const uint2*)&Ps[(wr + g + 8) * PST + s16 * 8 + 2 * t];
            unsigned pa[4] = {u0.x, u1.x, u0.y, u1.y};
            #pragma unroll
            for (int j = 0; j < 16; j++) {
                uint2 vv = *(const uint2*)&Vc[(j * 8 + g) * VSTU + s16 * 8 + 2 * t];
                unsigned vb[2] = {vv.x, vv.y};
                mma16(oacc[j], pa, vb);
            }
        }
    };

    for (int kt = 0; kt < nkt; kt += 2) {
        body(kt,     scA, scB);
        body(kt + 1, scB, scA);
    }

    // ---- epilogue: Y fp16 pairs, feature-pair-permuted ----
    const float il0 = 1.f / lrow[0];
    const float il1 = 1.f / lrow[1];
    unsigned* y0 = Y + (((size_t)(b * T_ + q0 + wr + g)) * H_ + h) * 64;
    unsigned* y1 = y0 + (size_t)8 * H_ * 64;
    #pragma unroll
    for (int j = 0; j < 16; j++) {
        int pos = (j >> 1) * 8 + 2 * t + (j & 1);
        y0[pos] = pk2h(oacc[j][0] * il0, oacc[j][1] * il0);
        y1[pos] = pk2h(oacc[j][2] * il1, oacc[j][3] * il1);
    }
}

// ---------------------------------------------------------------------------
extern "C" void kernel_launch(void* const* d_in, const int* in_sizes, int n_in,
                              void* d_out, int out_size)
{
    const float* x    = (const float*)d_in[0];
    const float* cosb = (const float*)d_in[1];
    const float* sinb = (const float*)d_in[2];
    const float* Wq   = (const float*)d_in[3];
    const float* Wk   = (const float*)d_in[4];
    const float* Wv   = (const float*)d_in[5];
    const float* Wo   = (const float*)d_in[6];
    float* out = (float*)d_out;

    unsigned *xc, *wqc, *wkc, *wvc, *woc, *qt, *ktp, *vperm, *y;
    cudaGetSymbolAddress((void**)&xc,    g_xc);
    cudaGetSymbolAddress((void**)&wqc,   g_wqc);
    cudaGetSymbolAddress((void**)&wkc,   g_wkc);
    cudaGetSymbolAddress((void**)&wvc,   g_wvc);
    cudaGetSymbolAddress((void**)&woc,   g_woc);
    cudaGetSymbolAddress((void**)&qt,    g_qt);
    cudaGetSymbolAddress((void**)&ktp,   g_kt);
    cudaGetSymbolAddress((void**)&vperm, g_vperm);
    cudaGetSymbolAddress((void**)&y,     g_y);

    cvt_all_kernel<<<NCVT16 / 256, 256>>>(
        (const float4*)x,  (uint4*)xc,
        (const float4*)Wq, (uint4*)wqc,
        (const float4*)Wk, (uint4*)wkc,
        (const float4*)Wv, (uint4*)wvc,
        (const float4*)Wo, (uint4*)woc);

    cudaFuncSetAttribute(qkv_gemm, cudaFuncAttributeMaxDynamicSharedMemorySize,
                         GEMM_SMEM);
    cudaFuncSetAttribute(out_gemm, cudaFuncAttributeMaxDynamicSharedMemorySize,
                         GEMM_SMEM);
    cudaFuncSetAttribute(flash_fp16, cudaFuncAttributeMaxDynamicSharedMemorySize,
                         FLASH_SMEM);

    qkv_gemm<<<dim3(24, 16), 256, GEMM_SMEM>>>(xc, wqc, wkc, wvc, cosb, sinb,
                                               qt, ktp, vperm);

    flash_fp16<<<dim3(T_ / 128, B_ * H_), 256, FLASH_SMEM>>>(qt, ktp, vperm, y);

    out_gemm<<<dim3(16, 16), 256, GEMM_SMEM>>>(y, woc, out, C_);
}

// round 16
// speedup vs baseline: 1.0236x; 1.0236x over previous
#include <cuda_runtime.h>
#include <cuda_fp16.h>
#include <math.h>
#include <stdint.h>

#define B_    2
#define T_    2048
#define C_    2048
#define H_    16
#define KVH_  4
#define D_    128
#define GROUPS_ (H_/KVH_)
#define EPS_  1.1920929e-07f

#define GK    2048              // K dim in halves
#define GKU   1024              // K dim in u32 (fp16 pairs)
#define BKU   32                // u32 per iter (= 64 halves)
#define NIT   32

// ---------------- scratch (device globals; fp16 data as u32 pairs) ---------
__device__ unsigned g_xc  [B_*T_*GKU];
__device__ unsigned g_wqc [H_*D_*GKU];
__device__ unsigned g_wkc [KVH_*D_*GKU];
__device__ unsigned g_wvc [KVH_*D_*GKU];
__device__ unsigned g_woc [C_*GKU];
__device__ unsigned g_qt  [B_*T_*H_*64];        // [B,H,T,64u32] natural pairs
__device__ unsigned g_kt  [B_*T_*KVH_*64];      // [B,KVH,T,64u32] d-pair-PERMUTED
__device__ unsigned g_vperm[B_*KVH_*32*128*40]; // [B,KVH,ktile,128 d,40]
__device__ unsigned g_y   [B_*T_*H_*64];        // [B,T,H*64u32] pair-PERMUTED

// ---------------------------------------------------------------------------
// helpers
// ---------------------------------------------------------------------------
__device__ __forceinline__ unsigned pk2h(float a, float b) {
    __half2 h = __floats2half2_rn(a, b);
    return *(unsigned*)&h;
}

__device__ __forceinline__ float ex2(float x) {
    float y;
    asm("ex2.approx.ftz.f32 %0, %1;" : "=f"(y) : "f"(x));
    return y;
}

__device__ __forceinline__ uint32_t smem_u32(const void* p) {
    uint32_t a;
    asm("{ .reg .u64 t; cvta.to.shared.u64 t, %1; cvt.u32.u64 %0, t; }"
        : "=r"(a) : "l"(p));
    return a;
}

__device__ __forceinline__ void mma16(float* d, const unsigned* a, const unsigned* b) {
    asm volatile(
        "mma.sync.aligned.m16n8k16.row.col.f32.f16.f16.f32 "
        "{%0,%1,%2,%3}, {%4,%5,%6,%7}, {%8,%9}, {%0,%1,%2,%3};\n"
        : "+f"(d[0]), "+f"(d[1]), "+f"(d[2]), "+f"(d[3])
        : "r"(a[0]), "r"(a[1]), "r"(a[2]), "r"(a[3]), "r"(b[0]), "r"(b[1]));
}

#define CPC()  asm volatile("cp.async.commit_group;" ::: "memory")
#define CPW1() asm volatile("cp.async.wait_group 1;" ::: "memory")

// ---------------------------------------------------------------------------
// Fused fp16 pre-convert + pair-PERMUTE (one launch).
// ---------------------------------------------------------------------------
#define NX16  (B_*T_*C_/16)
#define NWQ16 (H_*D_*C_/16)
#define NWK16 (KVH_*D_*C_/16)
#define NCVT16 (NX16 + 2*NWQ16 + 2*NWK16)

__global__ __launch_bounds__(256) void cvt_all_kernel(
    const float4* __restrict__ x,  uint4* __restrict__ xc,
    const float4* __restrict__ wq, uint4* __restrict__ wqc,
    const float4* __restrict__ wk, uint4* __restrict__ wkc,
    const float4* __restrict__ wv, uint4* __restrict__ wvc,
    const float4* __restrict__ wo, uint4* __restrict__ woc)
{
    int i = blockIdx.x * 256 + threadIdx.x;
    const float4* src; uint4* dst; int off;
    if (i < NX16)                           { src = x;  dst = xc;  off = 0; }
    else if (i < NX16 + NWQ16)              { src = wq; dst = wqc; off = NX16; }
    else if (i < NX16 + NWQ16 + NWK16)      { src = wk; dst = wkc; off = NX16 + NWQ16; }
    else if (i < NX16 + NWQ16 + 2*NWK16)    { src = wv; dst = wvc; off = NX16 + NWQ16 + NWK16; }
    else                                    { src = wo; dst = woc; off = NX16 + NWQ16 + 2*NWK16; }
    int j = i - off;
    float4 v0 = src[4*j], v1 = src[4*j+1], v2 = src[4*j+2], v3 = src[4*j+3];
    dst[2*j]   = make_uint4(pk2h(v0.x, v0.y), pk2h(v2.x, v2.y),
                            pk2h(v0.z, v0.w), pk2h(v2.z, v2.w));
    dst[2*j+1] = make_uint4(pk2h(v1.x, v1.y), pk2h(v3.x, v3.y),
                            pk2h(v1.z, v1.w), pk2h(v3.z, v3.w));
}

// ---------------------------------------------------------------------------
// fp16 GEMM machinery (R14-proven, unchanged).
// ---------------------------------------------------------------------------
#define GST 40
#define TAW (256 * GST)
#define TWW (128 * GST)
#define STGW (TAW + TWW)
#define STGB (STGW * 4)
#define GEMM_SMEM (3 * STGB)             // 184320 B

__device__ __forceinline__ void issue_tile(uint32_t stg, const unsigned* Ab,
                                           const unsigned* Wb, int k0u, int tid)
{
    #pragma unroll
    for (int l = 0; l < 8; l++) {
        int idx = tid + l * 256;
        int r  = idx >> 3;
        int c4 = (idx & 7) * 4;
        asm volatile("cp.async.cg.shared.global [%0], [%1], 16;"
            :: "r"(stg + (uint32_t)(r * GST + c4) * 4),
               "l"(Ab + (size_t)r * GKU + k0u + c4));
    }
    #pragma unroll
    for (int l = 0; l < 4; l++) {
        int idx = tid + l * 256;
        int r  = idx >> 3;
        int c4 = (idx & 7) * 4;
        asm volatile("cp.async.cg.shared.global [%0], [%1], 16;"
            :: "r"(stg + (uint32_t)(TAW + r * GST + c4) * 4),
               "l"(Wb + (size_t)r * GKU + k0u + c4));
    }
}

__device__ __forceinline__ void mma_tile(const unsigned* As, const unsigned* Ws,
                                         int wm, int wn, int g, int t,
                                         float acc[4][8][4]) {
    #pragma unroll
    for (int s16 = 0; s16 < 4; s16++) {
        const int ko = s16 * 8 + 2 * t;
        unsigned a[4][4], b[8][2];
        #pragma unroll
        for (int mi = 0; mi < 4; mi++) {
            int r = wm + mi * 16;
            uint2 v0 = *(const uint2*)&As[(r + g)     * GST + ko];
            uint2 v1 = *(const uint2*)&As[(r + g + 8) * GST + ko];
            a[mi][0] = v0.x; a[mi][2] = v0.y;
            a[mi][1] = v1.x; a[mi][3] = v1.y;
        }
        #pragma unroll
        for (int j = 0; j < 8; j++) {
            uint2 v = *(const uint2*)&Ws[(wn + j * 8 + g) * GST + ko];
            b[j][0] = v.x; b[j][1] = v.y;
        }
        #pragma unroll
        for (int mi = 0; mi < 4; mi++)
            #pragma unroll
            for (int j = 0; j < 8; j++)
                mma16(acc[mi][j], a[mi], b[j]);
    }
}

#define GEMM_MAINLOOP(Ab, Wb)                                                  \
    float acc[4][8][4];                                                        \
    _Pragma("unroll")                                                          \
    for (int mi = 0; mi < 4; mi++)                                             \
        _Pragma("unroll")                                                      \
        for (int j = 0; j < 8; j++)                                            \
            _Pragma("unroll")                                                  \
            for (int c = 0; c < 4; c++) acc[mi][j][c] = 0.f;                   \
    {                                                                          \
        const uint32_t sb0 = smem_u32(sm);                                     \
        issue_tile(sb0,        Ab, Wb, 0,   tid); CPC();                       \
        issue_tile(sb0 + STGB, Ab, Wb, BKU, tid); CPC();                       \
        for (int it = 0; it < NIT; it++) {                                     \
            CPW1();                                                            \
            __syncthreads();                                                   \
            const int s = it - (it / 3) * 3;                                   \
            const unsigned* Ac = sm + s * STGW;                                \
            const unsigned* Wc = Ac + TAW;                                     \
            mma_tile(Ac, Wc, wm, wn, g, t, acc);                               \
            if (it + 2 < NIT) {                                                \
                const int sn = (it + 2) - ((it + 2) / 3) * 3;                  \
                issue_tile(sb0 + sn * STGB, Ab, Wb, (it + 2) * BKU, tid);      \
            }                                                                  \
            CPC();                                                             \
        }                                                                      \
    }

// ---------------------------------------------------------------------------
// Fused QKV projection + RoPE + RMSNorm epilogue (R14-proven, unchanged).
// ---------------------------------------------------------------------------
__global__ __launch_bounds__(256, 1) void qkv_gemm(
    const unsigned* __restrict__ x,
    const unsigned* __restrict__ Wq, const unsigned* __restrict__ Wk,
    const unsigned* __restrict__ Wv,
    const float* __restrict__ cosb, const float* __restrict__ sinb,
    unsigned* __restrict__ qt, unsigned* __restrict__ kt,
    unsigned* __restrict__ vperm)
{
    extern __shared__ unsigned sm[];

    const int tid  = threadIdx.x;
    const int lane = tid & 31;
    const int wid  = tid >> 5;
    const int g    = lane >> 2;
    const int t    = lane & 3;
    const int wm = (wid & 3) * 64;
    const int wn = (wid >> 2) * 64;
    const int m0 = blockIdx.y * 256;
    const int nb = blockIdx.x;

    const unsigned* W;
    if (nb < 16)      W = Wq + (size_t)nb * 128 * GKU;
    else if (nb < 20) W = Wk + (size_t)(nb - 16) * 128 * GKU;
    else              W = Wv + (size_t)(nb - 20) * 128 * GKU;
    const unsigned* Ab = x + (size_t)m0 * GKU;
    const unsigned* Wb = W;

    GEMM_MAINLOOP(Ab, Wb)

    __syncthreads();
    float* St = (float*)sm;
    #pragma unroll
    for (int mi = 0; mi < 4; mi++) {
        int r0 = wm + mi * 16 + g;
        #pragma unroll
        for (int j = 0; j < 8; j++) {
            int cc = wn + j * 8 + 2 * t;
            St[r0 * 132 + cc]           = acc[mi][j][0];
            St[r0 * 132 + cc + 1]       = acc[mi][j][1];
            St[(r0 + 8) * 132 + cc]     = acc[mi][j][2];
            St[(r0 + 8) * 132 + cc + 1] = acc[mi][j][3];
        }
    }
    __syncthreads();

    if (nb >= 20) {
        const int kvh = nb - 20;
        const int bidx = m0 >> 11;
        const int kt0  = (m0 & (T_ - 1)) >> 6;
        #pragma unroll
        for (int l = 0; l < 64; l++) {
            int idx = tid + l * 256;
            int c   = idx & 31;
            int d   = (idx >> 5) & 127;
            int kt4 = idx >> 12;
            int pl  = ((c & 7) >> 1) + ((c & 1) << 2);
            int kl  = (c >> 3) * 16 + 2 * pl;
            int row = kt4 * 64 + kl;
            unsigned val = pk2h(St[row * 132 + d], St[(row + 1) * 132 + d]);
            vperm[((size_t)((bidx * KVH_ + kvh) * 32 + kt0 + kt4) * 128 + d) * 40 + c] = val;
        }
        return;
    }

    const float scale = (nb < 16) ? 0.12751744843f : 1.0f;
    #pragma unroll
    for (int round = 0; round < 2; round++) {
        const int r  = (tid >> 1) + round * 128;
        const int hf = tid & 1;
        const int m  = m0 + r;
        const int bb = m >> 11;
        const int tt = m & (T_ - 1);

        const float* cr = cosb + tt * 64 + hf * 32;
        const float* sr = sinb + tt * 64 + hf * 32;
        const float* x1p = St + r * 132 + hf * 32;
        const float* x2p = x1p + 64;

        float o1[32], o2[32];
        float ss = 0.f;
        #pragma unroll
        for (int jj = 0; jj < 32; jj += 4) {
            float4 x1 = *(const float4*)(x1p + jj);
            float4 x2 = *(const float4*)(x2p + jj);
            float4 cv = *(const float4*)(cr + jj);
            float4 sv = *(const float4*)(sr + jj);
            float a0 = x1.x * cv.x + x2.x * sv.x, b0 = x2.x * cv.x - x1.x * sv.x;
            float a1 = x1.y * cv.y + x2.y * sv.y, b1 = x2.y * cv.y - x1.y * sv.y;
            float a2 = x1.z * cv.z + x2.z * sv.z, b2 = x2.z * cv.z - x1.z * sv.z;
            float a3 = x1.w * cv.w + x2.w * sv.w, b3 = x2.w * cv.w - x1.w * sv.w;
            o1[jj] = a0; o1[jj+1] = a1; o1[jj+2] = a2; o1[jj+3] = a3;
            o2[jj] = b0; o2[jj+1] = b1; o2[jj+2] = b2; o2[jj+3] = b3;
            ss += a0*a0 + b0*b0 + a1*a1 + b1*b1 + a2*a2 + b2*b2 + a3*a3 + b3*b3;
        }
        ss += __shfl_xor_sync(0xffffffffu, ss, 1);
        const float rr = rsqrtf(ss * (1.f / 128.f) + EPS_) * scale;

        if (nb < 16) {
            unsigned* ob = qt + (((size_t)(bb * H_ + nb) * T_ + tt) * 64);
            #pragma unroll
            for (int pj = 0; pj < 16; pj += 4) {
                *(uint4*)(ob + hf * 16 + pj) = make_uint4(
                    pk2h(o1[2*pj]   * rr, o1[2*pj+1] * rr),
                    pk2h(o1[2*pj+2] * rr, o1[2*pj+3] * rr),
                    pk2h(o1[2*pj+4] * rr, o1[2*pj+5] * rr),
                    pk2h(o1[2*pj+6] * rr, o1[2*pj+7] * rr));
                *(uint4*)(ob + 32 + hf * 16 + pj) = make_uint4(
                    pk2h(o2[2*pj]   * rr, o2[2*pj+1] * rr),
                    pk2h(o2[2*pj+2] * rr, o2[2*pj+3] * rr),
                    pk2h(o2[2*pj+4] * rr, o2[2*pj+5] * rr),
                    pk2h(o2[2*pj+6] * rr, o2[2*pj+7] * rr));
            }
        } else {
            unsigned* ob = kt + (((size_t)(bb * KVH_ + (nb - 16)) * T_ + tt) * 64);
            #pragma unroll
            for (int pj = 0; pj < 16; pj++) {
                int p1 = hf * 16 + pj;
                int pos1 = (p1 & ~7) + 2 * (p1 & 3) + ((p1 >> 2) & 1);
                ob[pos1] = pk2h(o1[2*pj] * rr, o1[2*pj+1] * rr);
                int p2 = p1 + 32;
                int pos2 = (p2 & ~7) + 2 * (p2 & 3) + ((p2 >> 2) & 1);
                ob[pos2] = pk2h(o2[2*pj] * rr, o2[2*pj+1] * rr);
            }
        }
    }
}

// ---------------------------------------------------------------------------
// Plain GEMM (output projection; R14-proven, unchanged). grid = (16, 16)
// ---------------------------------------------------------------------------
__global__ __launch_bounds__(256, 1) void out_gemm(
    const unsigned* __restrict__ A, const unsigned* __restrict__ W,
    float* __restrict__ C, int N)
{
    extern __shared__ unsigned sm[];

    const int tid  = threadIdx.x;
    const int lane = tid & 31;
    const int wid  = tid >> 5;
    const int g    = lane >> 2;
    const int t    = lane & 3;
    const int wm = (wid & 3) * 64;
    const int wn = (wid >> 2) * 64;
    const int m0 = blockIdx.y * 256;
    const int n0 = blockIdx.x * 128;

    const unsigned* Ab = A + (size_t)m0 * GKU;
    const unsigned* Wb = W + (size_t)n0 * GKU;

    GEMM_MAINLOOP(Ab, Wb)

    #pragma unroll
    for (int mi = 0; mi < 4; mi++) {
        int r0 = m0 + wm + mi * 16 + g;
        #pragma unroll
        for (int j = 0; j < 8; j++) {
            int cc = n0 + wn + j * 8 + 2 * t;
            *(float2*)(C + (size_t)r0 * N + cc) =
                make_float2(acc[mi][j][0], acc[mi][j][1]);
            *(float2*)(C + (size_t)(r0 + 8) * N + cc) =
                make_float2(acc[mi][j][2], acc[mi][j][3]);
        }
    }
}

// ---------------------------------------------------------------------------
// Causal flash attention fp16 (R14 structure + 3-stage K/V ring, ONE barrier
// per tile): Q in regs, cp.async, LDS.64 fragments, ex2 softmax.
// ---------------------------------------------------------------------------
#define KST 72
#define VSTU 40
#define PST 40
#define KBUF (64 * KST)                 // 4608 u32 / stage
#define VBUF (128 * VSTU)               // 5120 u32 / stage
#define VS_OFF (3 * KBUF)               // 13824
#define PS_OFF (VS_OFF + 3 * VBUF)      // 29184
#define FLASH_SMEM ((PS_OFF + 128 * PST) * 4)   // 137216 B

__global__ __launch_bounds__(256, 1) void flash_fp16(
    const unsigned* __restrict__ Qt, const unsigned* __restrict__ Kt,
    const unsigned* __restrict__ Vperm, unsigned* __restrict__ Y)
{
    extern __shared__ unsigned smu[];

    const int tid  = threadIdx.x;
    const int lane = tid & 31;
    const int wid  = tid >> 5;
    const int g    = lane >> 2;
    const int t    = lane & 3;
    const int qb = (gridDim.x - 1) - blockIdx.x;   // heavy-first
    const int q0 = qb * 128;
    const int bh = blockIdx.y;
    const int b  = bh / H_;
    const int h  = bh % H_;
    const int kvh = h / GROUPS_;
    const int wr  = wid * 16;

    unsigned* Ps = smu + PS_OFF;
    const uint32_t sbase = smem_u32(smu);

    const unsigned* kbase = Kt + ((size_t)(b * KVH_ + kvh) * T_) * 64;
    const unsigned* vblock = Vperm + (size_t)(b * KVH_ + kvh) * 32 * VBUF;

    // ---- stage Q (natural pairs) via smem (area reused by K ring) ----
    unsigned qreg[8][4];
    {
        const unsigned* qbase = Qt + ((size_t)bh * T_ + q0) * 64;
        #pragma unroll
        for (int l = 0; l < 8; l++) {
            int idx = tid + l * 256;       // 128 rows x 16 uint4 chunks
            int r  = idx >> 4;
            int c4 = (idx & 15) * 4;
            *(uint4*)&smu[r * 64 + c4] = *(const uint4*)(qbase + (size_t)r * 64 + c4);
        }
        __syncthreads();
        #pragma unroll
        for (int s16 = 0; s16 < 8; s16++) {
            qreg[s16][0] = smu[(wr + g)     * 64 + s16 * 8 + t];
            qreg[s16][1] = smu[(wr + g + 8) * 64 + s16 * 8 + t];
            qreg[s16][2] = smu[(wr + g)     * 64 + s16 * 8 + t + 4];
            qreg[s16][3] = smu[(wr + g + 8) * 64 + s16 * 8 + t + 4];
        }
        __syncthreads();
    }

    auto issue_kv = [&](int kt, int s) {
        const int k0 = kt * 64;
        const uint32_t kdst = sbase + (uint32_t)(s * KBUF) * 4;
        #pragma unroll
        for (int l = 0; l < 4; l++) {
            int idx = tid + l * 256;       // 64 rows x 16 chunks
            int r  = idx >> 4;
            int c4 = (idx & 15) * 4;
            asm volatile("cp.async.cg.shared.global [%0], [%1], 16;"
                :: "r"(kdst + (uint32_t)(r * KST + c4) * 4),
                   "l"(kbase + (size_t)(k0 + r) * 64 + c4));
        }
        const unsigned* vsrc = vblock + (size_t)kt * VBUF;
        const uint32_t vdst = sbase + (uint32_t)(VS_OFF + s * VBUF) * 4;
        #pragma unroll
        for (int l = 0; l < 5; l++) {
            int idx = tid + l * 256;       // 1280 chunks exactly
            asm volatile("cp.async.cg.shared.global [%0], [%1], 16;"
                :: "r"(vdst + (uint32_t)idx * 16),
                   "l"(vsrc + (size_t)idx * 4));
        }
    };

    float oacc[16][4];
    #pragma unroll
    for (int j = 0; j < 16; j++)
        #pragma unroll
        for (int c = 0; c < 4; c++) oacc[j][c] = 0.f;
    float mrow[2] = {-INFINITY, -INFINITY};
    float lrow[2] = {0.f, 0.f};

    const int nkt = qb * 2 + 2;
    issue_kv(0, 0); CPC();
    issue_kv(1, 1); CPC();

    for (int kt = 0; kt < nkt; kt++) {
        CPW1();
        __syncthreads();                  // kv(kt) resident; prior reads done
        const int s = kt - (kt / 3) * 3;
        const unsigned* Kc = smu + s * KBUF;
        const unsigned* Vc = smu + VS_OFF + s * VBUF;
        const int k0 = kt * 64;

        // ---- S = Q . K^T ----
        float sc[8][4];
        #pragma unroll
        for (int j = 0; j < 8; j++)
            #pragma unroll
            for (int c = 0; c < 4; c++) sc[j][c] = 0.f;

        #pragma unroll
        for (int s16 = 0; s16 < 8; s16++) {
            #pragma unroll
            for (int j = 0; j < 8; j++) {
                uint2 kv = *(const uint2*)&Kc[(j * 8 + g) * KST + s16 * 8 + 2 * t];
                unsigned kb[2] = {kv.x, kv.y};
                mma16(sc[j], qreg[s16], kb);
            }
        }

        if (kt >= nkt - 2) {
            int row0 = q0 + wr + g;
            int row1 = row0 + 8;
            #pragma unroll
            for (int j = 0; j < 8; j++) {
                int c0 = k0 + j * 8 + 2 * t;
                int c1 = c0 + 1;
                if (c0 > row0) sc[j][0] = -1e30f;
                if (c1 > row0) sc[j][1] = -1e30f;
                if (c0 > row1) sc[j][2] = -1e30f;
                if (c1 > row1) sc[j][3] = -1e30f;
            }
        }

        #pragma unroll
        for (int ri = 0; ri < 2; ri++) {
            const int i0 = ri * 2, i1 = ri * 2 + 1;
            float mx = -1e30f;
            #pragma unroll
            for (int j = 0; j < 8; j++)
                mx = fmaxf(mx, fmaxf(sc[j][i0], sc[j][i1]));
            mx = fmaxf(mx, __shfl_xor_sync(0xffffffffu, mx, 1));
            mx = fmaxf(mx, __shfl_xor_sync(0xffffffffu, mx, 2));
            float mnew = fmaxf(mrow[ri], mx);
            float alpha = ex2(mrow[ri] - mnew);
            float rs = 0.f;
            #pragma unroll
            for (int j = 0; j < 8; j++) {
                float p0 = ex2(sc[j][i0] - mnew);
                float p1 = ex2(sc[j][i1] - mnew);
                sc[j][i0] = p0; sc[j][i1] = p1;
                rs += p0 + p1;
            }
            rs += __shfl_xor_sync(0xffffffffu, rs, 1);
            rs += __shfl_xor_sync(0xffffffffu, rs, 2);
            lrow[ri] = lrow[ri] * alpha + rs;
            mrow[ri] = mnew;
            #pragma unroll
            for (int j = 0; j < 16; j++) {
                oacc[j][i0] *= alpha;
                oacc[j][i1] *= alpha;
            }
        }

        // ---- write P (fp16 pairs, key-pair-permuted positions) ----
        #pragma unroll
        for (int j = 0; j < 8; j++) {
            int pos = (j >> 1) * 8 + 2 * t + (j & 1);
            Ps[(wr + g)     * PST + pos] = pk2h(sc[j][0], sc[j][1]);
            Ps[(wr + g + 8) * PST + pos] = pk2h(sc[j][2], sc[j][3]);
        }
        __syncwarp();

        // ---- O += P . V ----
        #pragma unroll
        for (int s16 = 0; s16 < 4; s16++) {
            uint2 u0 = *(const uint2*)&Ps[(wr + g)     * PST + s16 * 8 + 2 * t];
            uint2 u1 = *(const uint2*)&Ps[(wr + g + 8) * PST + s16 * 8 + 2 * t];
            unsigned pa[4] = {u0.x, u1.x, u0.y, u1.y};
            #pragma unroll
            for (int j = 0; j < 16; j++) {
                uint2 vv = *(const uint2*)&Vc[(j * 8 + g) * VSTU + s16 * 8 + 2 * t];
                unsigned vb[2] = {vv.x, vv.y};
                mma16(oacc[j], pa, vb);
            }
        }

        // 3-stage ring: stage (kt+2)%3 was last read at iter kt-1, which all
        // warps completed before this iter's top barrier -> no bottom barrier.
        if (kt + 2 < nkt) {
            const int sn = (kt + 2) - ((kt + 2) / 3) * 3;
            issue_kv(kt + 2, sn);
        }
        CPC();
    }

    // ---- epilogue: Y fp16 pairs, feature-pair-permuted ----
    const float il0 = 1.f / lrow[0];
    const float il1 = 1.f / lrow[1];
    unsigned* y0 = Y + (((size_t)(b * T_ + q0 + wr + g)) * H_ + h) * 64;
    unsigned* y1 = y0 + (size_t)8 * H_ * 64;
    #pragma unroll
    for (int j = 0; j < 16; j++) {
        int pos = (j >> 1) * 8 + 2 * t + (j & 1);
        y0[pos] = pk2h(oacc[j][0] * il0, oacc[j][1] * il0);
        y1[pos] = pk2h(oacc[j][2] * il1, oacc[j][3] * il1);
    }
}

// ---------------------------------------------------------------------------
extern "C" void kernel_launch(void* const* d_in, const int* in_sizes, int n_in,
                              void* d_out, int out_size)
{
    const float* x    = (const float*)d_in[0];
    const float* cosb = (const float*)d_in[1];
    const float* sinb = (const float*)d_in[2];
    const float* Wq   = (const float*)d_in[3];
    const float* Wk   = (const float*)d_in[4];
    const float* Wv   = (const float*)d_in[5];
    const float* Wo   = (const float*)d_in[6];
    float* out = (float*)d_out;

    unsigned *xc, *wqc, *wkc, *wvc, *woc, *qt, *ktp, *vperm, *y;
    cudaGetSymbolAddress((void**)&xc,    g_xc);
    cudaGetSymbolAddress((void**)&wqc,   g_wqc);
    cudaGetSymbolAddress((void**)&wkc,   g_wkc);
    cudaGetSymbolAddress((void**)&wvc,   g_wvc);
    cudaGetSymbolAddress((void**)&woc,   g_woc);
    cudaGetSymbolAddress((void**)&qt,    g_qt);
    cudaGetSymbolAddress((void**)&ktp,   g_kt);
    cudaGetSymbolAddress((void**)&vperm, g_vperm);
    cudaGetSymbolAddress((void**)&y,     g_y);

    cvt_all_kernel<<<NCVT16 / 256, 256>>>(
        (const float4*)x,  (uint4*)xc,
        (const float4*)Wq, (uint4*)wqc,
        (const float4*)Wk, (uint4*)wkc,
        (const float4*)Wv, (uint4*)wvc,
        (const float4*)Wo, (uint4*)woc);

    cudaFuncSetAttribute(qkv_gemm, cudaFuncAttributeMaxDynamicSharedMemorySize,
                         GEMM_SMEM);
    cudaFuncSetAttribute(out_gemm, cudaFuncAttributeMaxDynamicSharedMemorySize,
                         GEMM_SMEM);
    cudaFuncSetAttribute(flash_fp16, cudaFuncAttributeMaxDynamicSharedMemorySize,
                         FLASH_SMEM);

    qkv_gemm<<<dim3(24, 16), 256, GEMM_SMEM>>>(xc, wqc, wkc, wvc, cosb, sinb,
                                               qt, ktp, vperm);

    flash_fp16<<<dim3(T_ / 128, B_ * H_), 256, FLASH_SMEM>>>(qt, ktp, vperm, y);

    out_gemm<<<dim3(16, 16), 256, GEMM_SMEM>>>(y, woc, out, C_);
}